// round 1
// baseline (speedup 1.0000x reference)
#include <cuda_runtime.h>

#define B_  2
#define S_  2048
#define D_  1024
#define H_  16
#define DH_ 64

// Scratch (allocation-free rule: __device__ globals)
__device__ float g_q[B_ * S_ * D_];
__device__ float g_k[B_ * S_ * D_];
__device__ float g_v[B_ * S_ * D_];
__device__ float g_ctx[B_ * S_ * D_];

// ---------------------------------------------------------------------------
// SGEMM with bias: C[M,N] = A[M,K] @ W[K,N] + bias[N]
// 128x128 block tile, BK=8, 256 threads, 8x8 register tile per thread.
// Assumes M%128==0, N%128==0, K%8==0 (true for all shapes here).
// ---------------------------------------------------------------------------
#define GBM 128
#define GBN 128
#define GBK 8
#define GTM 8
#define GTN 8

__global__ void __launch_bounds__(256, 2)
sgemm_bias(const float* __restrict__ A, const float* __restrict__ W,
           const float* __restrict__ bias, float* __restrict__ C,
           int M, int N, int K)
{
    __shared__ float As[GBK][GBM];   // A^T chunk: As[k][m]
    __shared__ float Bs[GBK][GBN];   // Bs[k][n]

    const int tid = threadIdx.x;
    const int m0  = blockIdx.y * GBM;
    const int n0  = blockIdx.x * GBN;
    const int tm  = (tid / 16) * GTM;
    const int tn  = (tid % 16) * GTN;

    float acc[GTM][GTN];
    #pragma unroll
    for (int i = 0; i < GTM; i++)
        #pragma unroll
        for (int j = 0; j < GTN; j++)
            acc[i][j] = 0.0f;

    // load mapping
    const int arow = tid / 2;          // 0..127
    const int acol = (tid % 2) * 4;    // 0 or 4
    const int brow = tid / 32;         // 0..7
    const int bcol = (tid % 32) * 4;   // 0..124

    const float* Ab = A + (size_t)m0 * K;
    const float* Wb = W + n0;

    for (int k0 = 0; k0 < K; k0 += GBK) {
        float4 av = *(const float4*)(Ab + (size_t)arow * K + k0 + acol);
        As[acol + 0][arow] = av.x;
        As[acol + 1][arow] = av.y;
        As[acol + 2][arow] = av.z;
        As[acol + 3][arow] = av.w;
        float4 bv = *(const float4*)(Wb + (size_t)(k0 + brow) * N + bcol);
        *(float4*)&Bs[brow][bcol] = bv;
        __syncthreads();

        #pragma unroll
        for (int k = 0; k < GBK; k++) {
            float ra[GTM], rb[GTN];
            #pragma unroll
            for (int i = 0; i < GTM; i += 4)
                *(float4*)&ra[i] = *(const float4*)&As[k][tm + i];
            #pragma unroll
            for (int j = 0; j < GTN; j += 4)
                *(float4*)&rb[j] = *(const float4*)&Bs[k][tn + j];
            #pragma unroll
            for (int i = 0; i < GTM; i++)
                #pragma unroll
                for (int j = 0; j < GTN; j++)
                    acc[i][j] = fmaf(ra[i], rb[j], acc[i][j]);
        }
        __syncthreads();
    }

    // epilogue: bias + store
    #pragma unroll
    for (int i = 0; i < GTM; i++) {
        float* Cp = C + (size_t)(m0 + tm + i) * N + n0 + tn;
        #pragma unroll
        for (int j = 0; j < GTN; j += 4) {
            float4 b4 = *(const float4*)(bias + n0 + tn + j);
            float4 ov;
            ov.x = acc[i][j + 0] + b4.x;
            ov.y = acc[i][j + 1] + b4.y;
            ov.z = acc[i][j + 2] + b4.z;
            ov.w = acc[i][j + 3] + b4.w;
            *(float4*)(Cp + j) = ov;
        }
    }
}

// ---------------------------------------------------------------------------
// Flash attention, fp32, causal.
// Block = (b, h, 64-row q tile). 256 threads.
// Thread (w = tid/16, x = tid%16) owns O rows {w + 16i}, cols {x + 16j}, 4x4.
// K/V tiles of 64 rows streamed; online softmax with row stats in smem.
// smem (dynamic): Qt[64][65] (Q^T, scaled), Kt[64][65] (K^T), Vs[64][65],
//                 Ss[64][65], rowm/rowl/rowa[64]  -> 67,328 bytes
// ---------------------------------------------------------------------------
#define FA_SMEM ((4 * 64 * 65 + 3 * 64) * 4)

__global__ void __launch_bounds__(256)
flash_attn(const float* __restrict__ Q, const float* __restrict__ K,
           const float* __restrict__ V, float* __restrict__ ctx)
{
    extern __shared__ float sm[];
    float* Qt   = sm;                 // [64][65]  Qt[d][r]
    float* Kt   = Qt + 64 * 65;      // [64][65]  Kt[d][j]
    float* Vs   = Kt + 64 * 65;      // [64][65]  Vs[j][c]
    float* Ss   = Vs + 64 * 65;      // [64][65]  scores / P
    float* rowm = Ss + 64 * 65;      // [64]
    float* rowl = rowm + 64;         // [64]
    float* rowa = rowl + 64;         // [64]

    const int tid = threadIdx.x;
    const int w   = tid / 16;        // row group 0..15
    const int x   = tid % 16;        // col group 0..15
    const int bh  = blockIdx.y;
    const int b   = bh / H_;
    const int h   = bh % H_;
    const int q0  = blockIdx.x * 64;
    const size_t base = (size_t)b * S_ * D_ + (size_t)h * DH_;

    // Load Q tile transposed, pre-scaled by 1/sqrt(DH) = 0.125
    for (int idx = tid; idx < 64 * 64; idx += 256) {
        int r = idx / 64, c = idx % 64;        // c fast -> coalesced global
        Qt[c * 65 + r] = Q[base + (size_t)(q0 + r) * D_ + c] * 0.125f;
    }
    if (tid < 64) { rowm[tid] = -1e30f; rowl[tid] = 0.0f; }

    float o[4][4];
    #pragma unroll
    for (int i = 0; i < 4; i++)
        #pragma unroll
        for (int j = 0; j < 4; j++) o[i][j] = 0.0f;

    __syncthreads();

    const int ktiles = blockIdx.x + 1;   // causal: only tiles with k0 <= q0
    for (int kt = 0; kt < ktiles; kt++) {
        const int k0 = kt * 64;
        // Load K (transposed) and V tiles
        for (int idx = tid; idx < 64 * 64; idx += 256) {
            int r = idx / 64, c = idx % 64;
            Kt[c * 65 + r] = K[base + (size_t)(k0 + r) * D_ + c];
            Vs[r * 65 + c] = V[base + (size_t)(k0 + r) * D_ + c];
        }
        __syncthreads();

        // S = (Q/8) @ K^T : 64x64x64
        float s[4][4];
        #pragma unroll
        for (int i = 0; i < 4; i++)
            #pragma unroll
            for (int j = 0; j < 4; j++) s[i][j] = 0.0f;

        #pragma unroll 4
        for (int d = 0; d < 64; d++) {
            float ra[4], rb[4];
            #pragma unroll
            for (int i = 0; i < 4; i++) ra[i] = Qt[d * 65 + w + i * 16];
            #pragma unroll
            for (int j = 0; j < 4; j++) rb[j] = Kt[d * 65 + x + j * 16];
            #pragma unroll
            for (int i = 0; i < 4; i++)
                #pragma unroll
                for (int j = 0; j < 4; j++)
                    s[i][j] = fmaf(ra[i], rb[j], s[i][j]);
        }

        // Write masked scores to smem
        const bool diag = (kt == blockIdx.x);
        #pragma unroll
        for (int i = 0; i < 4; i++) {
            const int r = w + i * 16;
            #pragma unroll
            for (int j = 0; j < 4; j++) {
                const int c = x + j * 16;
                float val = s[i][j];
                if (diag && (k0 + c > q0 + r)) val = -1e30f;
                Ss[r * 65 + c] = val;
            }
        }
        __syncthreads();

        // Online softmax: one thread per row
        if (tid < 64) {
            const int r = tid;
            float m  = rowm[r];
            float mt = -1e30f;
            #pragma unroll 8
            for (int c = 0; c < 64; c++) mt = fmaxf(mt, Ss[r * 65 + c]);
            const float mn    = fmaxf(m, mt);
            const float alpha = __expf(m - mn);
            float l = rowl[r] * alpha;
            #pragma unroll 8
            for (int c = 0; c < 64; c++) {
                float p = __expf(Ss[r * 65 + c] - mn);
                Ss[r * 65 + c] = p;
                l += p;
            }
            rowm[r] = mn; rowl[r] = l; rowa[r] = alpha;
        }
        __syncthreads();

        // Rescale O, then O += P @ V
        float al[4];
        #pragma unroll
        for (int i = 0; i < 4; i++) al[i] = rowa[w + i * 16];
        #pragma unroll
        for (int i = 0; i < 4; i++)
            #pragma unroll
            for (int j = 0; j < 4; j++) o[i][j] *= al[i];

        #pragma unroll 4
        for (int jj = 0; jj < 64; jj++) {
            float pa[4], vb[4];
            #pragma unroll
            for (int i = 0; i < 4; i++) pa[i] = Ss[(w + i * 16) * 65 + jj];
            #pragma unroll
            for (int j = 0; j < 4; j++) vb[j] = Vs[jj * 65 + x + j * 16];
            #pragma unroll
            for (int i = 0; i < 4; i++)
                #pragma unroll
                for (int j = 0; j < 4; j++)
                    o[i][j] = fmaf(pa[i], vb[j], o[i][j]);
        }
        __syncthreads();
    }

    // Normalize and write ctx in [B,S,D] layout (head h -> cols h*64..h*64+63)
    #pragma unroll
    for (int i = 0; i < 4; i++) {
        const int r = w + i * 16;
        const float inv = 1.0f / rowl[r];
        #pragma unroll
        for (int j = 0; j < 4; j++) {
            const int c = x + j * 16;
            ctx[base + (size_t)(q0 + r) * D_ + c] = o[i][j] * inv;
        }
    }
}

// ---------------------------------------------------------------------------
// Launch: Q/K/V projections -> flash attention -> output projection.
// Inputs (metadata order): query, key, value, mask, Wq, bq, Wk, bk, Wv, bv, Wo, bo
// mask (d_in[3]) is the causal triu mask; we apply causality analytically.
// ---------------------------------------------------------------------------
extern "C" void kernel_launch(void* const* d_in, const int* in_sizes, int n_in,
                              void* d_out, int out_size)
{
    const float* query = (const float*)d_in[0];
    const float* key   = (const float*)d_in[1];
    const float* value = (const float*)d_in[2];
    const float* Wq    = (const float*)d_in[4];
    const float* bq    = (const float*)d_in[5];
    const float* Wk    = (const float*)d_in[6];
    const float* bk    = (const float*)d_in[7];
    const float* Wv    = (const float*)d_in[8];
    const float* bv    = (const float*)d_in[9];
    const float* Wo    = (const float*)d_in[10];
    const float* bo    = (const float*)d_in[11];
    float* out = (float*)d_out;

    float *qb, *kb, *vb, *cb;
    cudaGetSymbolAddress((void**)&qb, g_q);
    cudaGetSymbolAddress((void**)&kb, g_k);
    cudaGetSymbolAddress((void**)&vb, g_v);
    cudaGetSymbolAddress((void**)&cb, g_ctx);

    cudaFuncSetAttribute(flash_attn, cudaFuncAttributeMaxDynamicSharedMemorySize,
                         FA_SMEM);

    const int M = B_ * S_;           // 4096
    dim3 gemm_grid(D_ / GBN, M / GBM);   // (8, 32)

    sgemm_bias<<<gemm_grid, 256>>>(query, Wq, bq, qb, M, D_, D_);
    sgemm_bias<<<gemm_grid, 256>>>(key,   Wk, bk, kb, M, D_, D_);
    sgemm_bias<<<gemm_grid, 256>>>(value, Wv, bv, vb, M, D_, D_);

    dim3 fa_grid(S_ / 64, B_ * H_);      // (32, 32)
    flash_attn<<<fa_grid, 256, FA_SMEM>>>(qb, kb, vb, cb);

    sgemm_bias<<<gemm_grid, 256>>>(cb, Wo, bo, out, M, D_, D_);
}

// round 3
// speedup vs baseline: 1.3905x; 1.3905x over previous
#include <cuda_runtime.h>
#include <cuda_bf16.h>
#include <cstdint>

#define B_  2
#define S_  2048
#define D_  1024
#define H_  16
#define DH_ 64
#define MROWS (B_*S_)   // 4096

// Scratch (allocation-free rule: __device__ globals)
__device__ float g_q[B_ * S_ * D_];
__device__ float g_k[B_ * S_ * D_];
__device__ float g_v[B_ * S_ * D_];
__device__ float g_ctx[B_ * S_ * D_];
__device__ __nv_bfloat16 g_whi[4][D_ * D_];   // W^T hi split, [n][k]
__device__ __nv_bfloat16 g_wlo[4][D_ * D_];   // W^T lo split, [n][k]

// ---------------------------------------------------------------------------
// HMMA helper: D = A(16x16 bf16) @ B(16x8 bf16) + D (fp32)
// ---------------------------------------------------------------------------
__device__ __forceinline__ void mma16816(float* c, const uint32_t* a, const uint32_t* b) {
    asm volatile(
        "mma.sync.aligned.m16n8k16.row.col.f32.bf16.bf16.f32 "
        "{%0,%1,%2,%3}, {%4,%5,%6,%7}, {%8,%9}, {%0,%1,%2,%3};"
        : "+f"(c[0]), "+f"(c[1]), "+f"(c[2]), "+f"(c[3])
        : "r"(a[0]), "r"(a[1]), "r"(a[2]), "r"(a[3]), "r"(b[0]), "r"(b[1]));
}

// fp32 pair -> packed bf16x2 hi + bf16x2 lo (hi/lo split for precision)
__device__ __forceinline__ void split2(float x, float y, uint32_t& hi, uint32_t& lo) {
    __nv_bfloat16 hx = __float2bfloat16(x), hy = __float2bfloat16(y);
    __nv_bfloat16 lx = __float2bfloat16(x - __bfloat162float(hx));
    __nv_bfloat16 ly = __float2bfloat16(y - __bfloat162float(hy));
    hi = ((uint32_t)__bfloat16_as_ushort(hy) << 16) | __bfloat16_as_ushort(hx);
    lo = ((uint32_t)__bfloat16_as_ushort(ly) << 16) | __bfloat16_as_ushort(lx);
}

// ---------------------------------------------------------------------------
// prep_w: W[k][n] fp32 -> Whi/Wlo[n][k] bf16 (transpose + hi/lo split)
// ---------------------------------------------------------------------------
__global__ void prep_w(const float* __restrict__ W,
                       __nv_bfloat16* __restrict__ Whi,
                       __nv_bfloat16* __restrict__ Wlo)
{
    __shared__ float t[32][33];
    const int n0 = blockIdx.x * 32, k0 = blockIdx.y * 32;
    const int tx = threadIdx.x, ty = threadIdx.y;
    #pragma unroll
    for (int j = 0; j < 32; j += 8)
        t[ty + j][tx] = W[(size_t)(k0 + ty + j) * D_ + n0 + tx];
    __syncthreads();
    #pragma unroll
    for (int j = 0; j < 32; j += 8) {
        float v = t[tx][ty + j];          // = W[k0+tx][n0+ty+j]
        __nv_bfloat16 h = __float2bfloat16(v);
        __nv_bfloat16 l = __float2bfloat16(v - __bfloat162float(h));
        size_t o = (size_t)(n0 + ty + j) * D_ + k0 + tx;
        Whi[o] = h;
        Wlo[o] = l;
    }
}

// ---------------------------------------------------------------------------
// HMMA GEMM, bf16 hi/lo 3-MMA split: C[M,N] = A @ W + bias
//   A fp32 [M,K]; W pre-split as Whi/Wlo[n][k] bf16.
// CTA tile 128x128, BK=32, 8 warps (2m x 4n), warp tile 64x32.
// smem tiles padded to 40 bf16/row (20 u32) -> conflict-free fragment loads.
// ---------------------------------------------------------------------------
#define PAD 20   // u32 per smem row (32 bf16 data + 8 pad)

__global__ void __launch_bounds__(256)
gemm_hmma(const float* __restrict__ A,
          const __nv_bfloat16* __restrict__ Whi,
          const __nv_bfloat16* __restrict__ Wlo,
          const float* __restrict__ bias, float* __restrict__ C)
{
    __shared__ __align__(16) uint32_t sAhi[128 * PAD];
    __shared__ __align__(16) uint32_t sAlo[128 * PAD];
    __shared__ __align__(16) uint32_t sBhi[128 * PAD];
    __shared__ __align__(16) uint32_t sBlo[128 * PAD];

    const int tid = threadIdx.x, wid = tid >> 5, lid = tid & 31;
    const int g = lid >> 2, tc = lid & 3;
    const int wm = wid & 1, wn = wid >> 1;   // warp 64x32 tile at (wm*64, wn*32)
    const int m0 = blockIdx.y * 128, n0 = blockIdx.x * 128;

    float acc[4][4][4];
    #pragma unroll
    for (int i = 0; i < 4; i++)
        #pragma unroll
        for (int j = 0; j < 4; j++)
            #pragma unroll
            for (int q = 0; q < 4; q++) acc[i][j][q] = 0.0f;

    // LDG index maps
    const int ma = tid >> 3, qa = tid & 7;   // A: row ma(+32i), float4 col qa
    const int nb = tid >> 2, qb = tid & 3;   // B: row nb(+64i), uint4 col qb

    float4 av[4];
    uint4 bh[2], bl[2];

    // prefetch chunk 0
    {
        #pragma unroll
        for (int i = 0; i < 4; i++)
            av[i] = *((const float4*)A + (size_t)(m0 + ma + i * 32) * (D_/4) + qa);
        #pragma unroll
        for (int i = 0; i < 2; i++) {
            size_t idx = (size_t)(n0 + nb + i * 64) * (D_/8) + qb;
            bh[i] = *((const uint4*)Whi + idx);
            bl[i] = *((const uint4*)Wlo + idx);
        }
    }

    const int NCH = D_ / 32;   // 32 chunks
    for (int ch = 0; ch < NCH; ch++) {
        // ---- STS: convert A to hi/lo, store; store B tiles ----
        #pragma unroll
        for (int i = 0; i < 4; i++) {
            uint2 h2, l2;
            split2(av[i].x, av[i].y, h2.x, l2.x);
            split2(av[i].z, av[i].w, h2.y, l2.y);
            int off = (ma + i * 32) * PAD + qa * 2;
            *(uint2*)&sAhi[off] = h2;
            *(uint2*)&sAlo[off] = l2;
        }
        #pragma unroll
        for (int i = 0; i < 2; i++) {
            int off = (nb + i * 64) * PAD + qb * 4;
            *(uint4*)&sBhi[off] = bh[i];
            *(uint4*)&sBlo[off] = bl[i];
        }
        __syncthreads();

        // ---- prefetch next chunk (overlaps MMA below) ----
        if (ch + 1 < NCH) {
            const int k0 = (ch + 1) * 32;
            #pragma unroll
            for (int i = 0; i < 4; i++)
                av[i] = *((const float4*)A + (size_t)(m0 + ma + i * 32) * (D_/4) + (k0 >> 2) + qa);
            #pragma unroll
            for (int i = 0; i < 2; i++) {
                size_t idx = (size_t)(n0 + nb + i * 64) * (D_/8) + (k0 >> 3) + qb;
                bh[i] = *((const uint4*)Whi + idx);
                bl[i] = *((const uint4*)Wlo + idx);
            }
        }

        // ---- compute: 2 k16-steps ----
        #pragma unroll
        for (int ks = 0; ks < 2; ks++) {
            const int kb = ks * 8 + tc;
            uint32_t ah[4][4], al[4][4];
            #pragma unroll
            for (int i = 0; i < 4; i++) {
                const int r0 = (wm * 64 + i * 16 + g) * PAD;
                const int r1 = r0 + 8 * PAD;
                ah[i][0] = sAhi[r0 + kb];     ah[i][1] = sAhi[r1 + kb];
                ah[i][2] = sAhi[r0 + kb + 4]; ah[i][3] = sAhi[r1 + kb + 4];
                al[i][0] = sAlo[r0 + kb];     al[i][1] = sAlo[r1 + kb];
                al[i][2] = sAlo[r0 + kb + 4]; al[i][3] = sAlo[r1 + kb + 4];
            }
            uint32_t bhf[4][2], blf[4][2];
            #pragma unroll
            for (int j = 0; j < 4; j++) {
                const int rn = (wn * 32 + j * 8 + g) * PAD;
                bhf[j][0] = sBhi[rn + kb]; bhf[j][1] = sBhi[rn + kb + 4];
                blf[j][0] = sBlo[rn + kb]; blf[j][1] = sBlo[rn + kb + 4];
            }
            #pragma unroll
            for (int i = 0; i < 4; i++)
                #pragma unroll
                for (int j = 0; j < 4; j++) {
                    mma16816(acc[i][j], ah[i], bhf[j]);
                    mma16816(acc[i][j], ah[i], blf[j]);
                    mma16816(acc[i][j], al[i], bhf[j]);
                }
        }
        __syncthreads();
    }

    // ---- epilogue: bias + store (float2 per fragment row) ----
    #pragma unroll
    for (int j = 0; j < 4; j++) {
        const int n = n0 + wn * 32 + j * 8 + tc * 2;
        const float2 b2 = *(const float2*)(bias + n);
        #pragma unroll
        for (int i = 0; i < 4; i++) {
            const int m = m0 + wm * 64 + i * 16 + g;
            float2 o0, o1;
            o0.x = acc[i][j][0] + b2.x; o0.y = acc[i][j][1] + b2.y;
            o1.x = acc[i][j][2] + b2.x; o1.y = acc[i][j][3] + b2.y;
            *(float2*)(C + (size_t)m * D_ + n) = o0;
            *(float2*)(C + (size_t)(m + 8) * D_ + n) = o1;
        }
    }
}

// ---------------------------------------------------------------------------
// Flash attention, fp32, causal. 64-row q tile per CTA, 256 threads.
// Parallel online softmax via width-16 shfl.xor; row stats in registers.
// smem: Qt[64][65], Kt[64][65], Vs[64][65], Ss[64][65] = 66,560 bytes
// ---------------------------------------------------------------------------
#define FA_SMEM (4 * 64 * 65 * 4)

__global__ void __launch_bounds__(256)
flash_attn(const float* __restrict__ Q, const float* __restrict__ K,
           const float* __restrict__ V, float* __restrict__ ctx)
{
    extern __shared__ float sfa[];
    float* Qt = sfa;                // [64][65]  Qt[d][r]
    float* Kt = Qt + 64 * 65;       // [64][65]  Kt[d][j]
    float* Vs = Kt + 64 * 65;       // [64][65]  Vs[j][c]
    float* Ss = Vs + 64 * 65;       // [64][65]  P

    const int tid = threadIdx.x;
    const int w   = tid / 16;
    const int x   = tid % 16;
    const int bh  = blockIdx.y;
    const int b   = bh / H_;
    const int h   = bh % H_;
    const int q0  = blockIdx.x * 64;
    const size_t base = (size_t)b * S_ * D_ + (size_t)h * DH_;

    for (int idx = tid; idx < 64 * 64; idx += 256) {
        int r = idx / 64, c = idx % 64;
        Qt[c * 65 + r] = Q[base + (size_t)(q0 + r) * D_ + c] * 0.125f;
    }

    float row_m[4], row_l[4];
    float o[4][4];
    #pragma unroll
    for (int i = 0; i < 4; i++) {
        row_m[i] = -1e30f; row_l[i] = 0.0f;
        #pragma unroll
        for (int j = 0; j < 4; j++) o[i][j] = 0.0f;
    }
    __syncthreads();

    const int ktiles = blockIdx.x + 1;
    for (int kt = 0; kt < ktiles; kt++) {
        const int k0 = kt * 64;
        for (int idx = tid; idx < 64 * 64; idx += 256) {
            int r = idx / 64, c = idx % 64;
            Kt[c * 65 + r] = K[base + (size_t)(k0 + r) * D_ + c];
            Vs[r * 65 + c] = V[base + (size_t)(k0 + r) * D_ + c];
        }
        __syncthreads();

        // S = (Q/8) @ K^T
        float s[4][4];
        #pragma unroll
        for (int i = 0; i < 4; i++)
            #pragma unroll
            for (int j = 0; j < 4; j++) s[i][j] = 0.0f;
        #pragma unroll 4
        for (int d = 0; d < 64; d++) {
            float ra[4], rb[4];
            #pragma unroll
            for (int i = 0; i < 4; i++) ra[i] = Qt[d * 65 + w + i * 16];
            #pragma unroll
            for (int j = 0; j < 4; j++) rb[j] = Kt[d * 65 + x + j * 16];
            #pragma unroll
            for (int i = 0; i < 4; i++)
                #pragma unroll
                for (int j = 0; j < 4; j++)
                    s[i][j] = fmaf(ra[i], rb[j], s[i][j]);
        }

        // causal mask (registers)
        if (kt == blockIdx.x) {
            #pragma unroll
            for (int i = 0; i < 4; i++) {
                const int r = q0 + w + i * 16;
                #pragma unroll
                for (int j = 0; j < 4; j++)
                    if (k0 + x + j * 16 > r) s[i][j] = -1e30f;
            }
        }

        // parallel online softmax: reduce across 16 lanes owning each row
        #pragma unroll
        for (int i = 0; i < 4; i++) {
            float mt = fmaxf(fmaxf(s[i][0], s[i][1]), fmaxf(s[i][2], s[i][3]));
            #pragma unroll
            for (int off = 8; off >= 1; off >>= 1)
                mt = fmaxf(mt, __shfl_xor_sync(0xffffffffu, mt, off));
            const float mn    = fmaxf(row_m[i], mt);
            const float alpha = __expf(row_m[i] - mn);
            row_m[i] = mn;
            float ls = 0.0f;
            #pragma unroll
            for (int j = 0; j < 4; j++) {
                float p = __expf(s[i][j] - mn);
                s[i][j] = p;
                ls += p;
            }
            #pragma unroll
            for (int off = 8; off >= 1; off >>= 1)
                ls += __shfl_xor_sync(0xffffffffu, ls, off);
            row_l[i] = row_l[i] * alpha + ls;
            #pragma unroll
            for (int j = 0; j < 4; j++) {
                o[i][j] *= alpha;
                Ss[(w + i * 16) * 65 + x + j * 16] = s[i][j];
            }
        }
        __syncthreads();

        // O += P @ V
        #pragma unroll 4
        for (int jj = 0; jj < 64; jj++) {
            float pa[4], vb[4];
            #pragma unroll
            for (int i = 0; i < 4; i++) pa[i] = Ss[(w + i * 16) * 65 + jj];
            #pragma unroll
            for (int j = 0; j < 4; j++) vb[j] = Vs[jj * 65 + x + j * 16];
            #pragma unroll
            for (int i = 0; i < 4; i++)
                #pragma unroll
                for (int j = 0; j < 4; j++)
                    o[i][j] = fmaf(pa[i], vb[j], o[i][j]);
        }
        __syncthreads();
    }

    #pragma unroll
    for (int i = 0; i < 4; i++) {
        const int r = w + i * 16;
        const float inv = 1.0f / row_l[i];
        #pragma unroll
        for (int j = 0; j < 4; j++) {
            const int c = x + j * 16;
            ctx[base + (size_t)(q0 + r) * D_ + c] = o[i][j] * inv;
        }
    }
}

// ---------------------------------------------------------------------------
// Launch
// Inputs: query, key, value, mask, Wq, bq, Wk, bk, Wv, bv, Wo, bo
// ---------------------------------------------------------------------------
extern "C" void kernel_launch(void* const* d_in, const int* in_sizes, int n_in,
                              void* d_out, int out_size)
{
    const float* query = (const float*)d_in[0];
    const float* key   = (const float*)d_in[1];
    const float* value = (const float*)d_in[2];
    const float* Wq    = (const float*)d_in[4];
    const float* bq    = (const float*)d_in[5];
    const float* Wk    = (const float*)d_in[6];
    const float* bk    = (const float*)d_in[7];
    const float* Wv    = (const float*)d_in[8];
    const float* bv    = (const float*)d_in[9];
    const float* Wo    = (const float*)d_in[10];
    const float* bo    = (const float*)d_in[11];
    float* out = (float*)d_out;

    float *qb, *kb, *vb, *cb;
    cudaGetSymbolAddress((void**)&qb, g_q);
    cudaGetSymbolAddress((void**)&kb, g_k);
    cudaGetSymbolAddress((void**)&vb, g_v);
    cudaGetSymbolAddress((void**)&cb, g_ctx);
    __nv_bfloat16 *whi, *wlo;
    cudaGetSymbolAddress((void**)&whi, g_whi);
    cudaGetSymbolAddress((void**)&wlo, g_wlo);

    cudaFuncSetAttribute(flash_attn, cudaFuncAttributeMaxDynamicSharedMemorySize, FA_SMEM);

    const size_t WSZ = (size_t)D_ * D_;
    dim3 pgrid(32, 32), pblk(32, 8);
    prep_w<<<pgrid, pblk>>>(Wq, whi + 0 * WSZ, wlo + 0 * WSZ);
    prep_w<<<pgrid, pblk>>>(Wk, whi + 1 * WSZ, wlo + 1 * WSZ);
    prep_w<<<pgrid, pblk>>>(Wv, whi + 2 * WSZ, wlo + 2 * WSZ);
    prep_w<<<pgrid, pblk>>>(Wo, whi + 3 * WSZ, wlo + 3 * WSZ);

    dim3 ggrid(D_ / 128, MROWS / 128);   // (8, 32)
    gemm_hmma<<<ggrid, 256>>>(query, whi + 0 * WSZ, wlo + 0 * WSZ, bq, qb);
    gemm_hmma<<<ggrid, 256>>>(key,   whi + 1 * WSZ, wlo + 1 * WSZ, bk, kb);
    gemm_hmma<<<ggrid, 256>>>(value, whi + 2 * WSZ, wlo + 2 * WSZ, bv, vb);

    dim3 fgrid(S_ / 64, B_ * H_);        // (32, 32)
    flash_attn<<<fgrid, 256, FA_SMEM>>>(qb, kb, vb, cb);

    gemm_hmma<<<ggrid, 256>>>(cb, whi + 3 * WSZ, wlo + 3 * WSZ, bo, out);
}

// round 4
// speedup vs baseline: 2.3676x; 1.7027x over previous
#include <cuda_runtime.h>
#include <cuda_bf16.h>
#include <cstdint>

#define B_  2
#define S_  2048
#define D_  1024
#define H_  16
#define DH_ 64
#define MROWS (B_*S_)   // 4096

// Scratch (allocation-free rule: __device__ globals)
__device__ float g_q[B_ * S_ * D_];
__device__ float g_k[B_ * S_ * D_];
__device__ float g_v[B_ * S_ * D_];
__device__ float g_ctx[B_ * S_ * D_];
__device__ __nv_bfloat16 g_whi[4][D_ * D_];   // W^T hi split, [n][k]
__device__ __nv_bfloat16 g_wlo[4][D_ * D_];   // W^T lo split, [n][k]

// ---------------------------------------------------------------------------
// HMMA helper: D = A(16x16 bf16) @ B(16x8 bf16) + D (fp32)
// ---------------------------------------------------------------------------
__device__ __forceinline__ void mma16816(float* c, const uint32_t* a, const uint32_t* b) {
    asm volatile(
        "mma.sync.aligned.m16n8k16.row.col.f32.bf16.bf16.f32 "
        "{%0,%1,%2,%3}, {%4,%5,%6,%7}, {%8,%9}, {%0,%1,%2,%3};"
        : "+f"(c[0]), "+f"(c[1]), "+f"(c[2]), "+f"(c[3])
        : "r"(a[0]), "r"(a[1]), "r"(a[2]), "r"(a[3]), "r"(b[0]), "r"(b[1]));
}

// fp32 pair -> packed bf16x2 hi + bf16x2 lo (hi/lo split for precision)
__device__ __forceinline__ void split2(float x, float y, uint32_t& hi, uint32_t& lo) {
    __nv_bfloat16 hx = __float2bfloat16(x), hy = __float2bfloat16(y);
    __nv_bfloat16 lx = __float2bfloat16(x - __bfloat162float(hx));
    __nv_bfloat16 ly = __float2bfloat16(y - __bfloat162float(hy));
    hi = ((uint32_t)__bfloat16_as_ushort(hy) << 16) | __bfloat16_as_ushort(hx);
    lo = ((uint32_t)__bfloat16_as_ushort(ly) << 16) | __bfloat16_as_ushort(lx);
}

// ---------------------------------------------------------------------------
// prep_w: W[k][n] fp32 -> Whi/Wlo[n][k] bf16 (transpose + hi/lo split)
// ---------------------------------------------------------------------------
__global__ void prep_w(const float* __restrict__ W,
                       __nv_bfloat16* __restrict__ Whi,
                       __nv_bfloat16* __restrict__ Wlo)
{
    __shared__ float t[32][33];
    const int n0 = blockIdx.x * 32, k0 = blockIdx.y * 32;
    const int tx = threadIdx.x, ty = threadIdx.y;
    #pragma unroll
    for (int j = 0; j < 32; j += 8)
        t[ty + j][tx] = W[(size_t)(k0 + ty + j) * D_ + n0 + tx];
    __syncthreads();
    #pragma unroll
    for (int j = 0; j < 32; j += 8) {
        float v = t[tx][ty + j];
        __nv_bfloat16 h = __float2bfloat16(v);
        __nv_bfloat16 l = __float2bfloat16(v - __bfloat162float(h));
        size_t o = (size_t)(n0 + ty + j) * D_ + k0 + tx;
        Whi[o] = h;
        Wlo[o] = l;
    }
}

// ---------------------------------------------------------------------------
// HMMA GEMM, bf16 hi/lo 3-MMA split: C[M,N] = A @ W + bias  (unchanged, passing)
// ---------------------------------------------------------------------------
#define PAD 20   // u32 per smem row (16 u32 data + 4 pad)

__global__ void __launch_bounds__(256)
gemm_hmma(const float* __restrict__ A,
          const __nv_bfloat16* __restrict__ Whi,
          const __nv_bfloat16* __restrict__ Wlo,
          const float* __restrict__ bias, float* __restrict__ C)
{
    __shared__ __align__(16) uint32_t sAhi[128 * PAD];
    __shared__ __align__(16) uint32_t sAlo[128 * PAD];
    __shared__ __align__(16) uint32_t sBhi[128 * PAD];
    __shared__ __align__(16) uint32_t sBlo[128 * PAD];

    const int tid = threadIdx.x, wid = tid >> 5, lid = tid & 31;
    const int g = lid >> 2, tc = lid & 3;
    const int wm = wid & 1, wn = wid >> 1;
    const int m0 = blockIdx.y * 128, n0 = blockIdx.x * 128;

    float acc[4][4][4];
    #pragma unroll
    for (int i = 0; i < 4; i++)
        #pragma unroll
        for (int j = 0; j < 4; j++)
            #pragma unroll
            for (int q = 0; q < 4; q++) acc[i][j][q] = 0.0f;

    const int ma = tid >> 3, qa = tid & 7;
    const int nb = tid >> 2, qb = tid & 3;

    float4 av[4];
    uint4 bh[2], bl[2];

    #pragma unroll
    for (int i = 0; i < 4; i++)
        av[i] = *((const float4*)A + (size_t)(m0 + ma + i * 32) * (D_/4) + qa);
    #pragma unroll
    for (int i = 0; i < 2; i++) {
        size_t idx = (size_t)(n0 + nb + i * 64) * (D_/8) + qb;
        bh[i] = *((const uint4*)Whi + idx);
        bl[i] = *((const uint4*)Wlo + idx);
    }

    const int NCH = D_ / 32;
    for (int ch = 0; ch < NCH; ch++) {
        #pragma unroll
        for (int i = 0; i < 4; i++) {
            uint2 h2, l2;
            split2(av[i].x, av[i].y, h2.x, l2.x);
            split2(av[i].z, av[i].w, h2.y, l2.y);
            int off = (ma + i * 32) * PAD + qa * 2;
            *(uint2*)&sAhi[off] = h2;
            *(uint2*)&sAlo[off] = l2;
        }
        #pragma unroll
        for (int i = 0; i < 2; i++) {
            int off = (nb + i * 64) * PAD + qb * 4;
            *(uint4*)&sBhi[off] = bh[i];
            *(uint4*)&sBlo[off] = bl[i];
        }
        __syncthreads();

        if (ch + 1 < NCH) {
            const int k0 = (ch + 1) * 32;
            #pragma unroll
            for (int i = 0; i < 4; i++)
                av[i] = *((const float4*)A + (size_t)(m0 + ma + i * 32) * (D_/4) + (k0 >> 2) + qa);
            #pragma unroll
            for (int i = 0; i < 2; i++) {
                size_t idx = (size_t)(n0 + nb + i * 64) * (D_/8) + (k0 >> 3) + qb;
                bh[i] = *((const uint4*)Whi + idx);
                bl[i] = *((const uint4*)Wlo + idx);
            }
        }

        #pragma unroll
        for (int ks = 0; ks < 2; ks++) {
            const int kb = ks * 8 + tc;
            uint32_t ah[4][4], al[4][4];
            #pragma unroll
            for (int i = 0; i < 4; i++) {
                const int r0 = (wm * 64 + i * 16 + g) * PAD;
                const int r1 = r0 + 8 * PAD;
                ah[i][0] = sAhi[r0 + kb];     ah[i][1] = sAhi[r1 + kb];
                ah[i][2] = sAhi[r0 + kb + 4]; ah[i][3] = sAhi[r1 + kb + 4];
                al[i][0] = sAlo[r0 + kb];     al[i][1] = sAlo[r1 + kb];
                al[i][2] = sAlo[r0 + kb + 4]; al[i][3] = sAlo[r1 + kb + 4];
            }
            uint32_t bhf[4][2], blf[4][2];
            #pragma unroll
            for (int j = 0; j < 4; j++) {
                const int rn = (wn * 32 + j * 8 + g) * PAD;
                bhf[j][0] = sBhi[rn + kb]; bhf[j][1] = sBhi[rn + kb + 4];
                blf[j][0] = sBlo[rn + kb]; blf[j][1] = sBlo[rn + kb + 4];
            }
            #pragma unroll
            for (int i = 0; i < 4; i++)
                #pragma unroll
                for (int j = 0; j < 4; j++) {
                    mma16816(acc[i][j], ah[i], bhf[j]);
                    mma16816(acc[i][j], ah[i], blf[j]);
                    mma16816(acc[i][j], al[i], bhf[j]);
                }
        }
        __syncthreads();
    }

    #pragma unroll
    for (int j = 0; j < 4; j++) {
        const int n = n0 + wn * 32 + j * 8 + tc * 2;
        const float2 b2 = *(const float2*)(bias + n);
        #pragma unroll
        for (int i = 0; i < 4; i++) {
            const int m = m0 + wm * 64 + i * 16 + g;
            float2 o0, o1;
            o0.x = acc[i][j][0] + b2.x; o0.y = acc[i][j][1] + b2.y;
            o1.x = acc[i][j][2] + b2.x; o1.y = acc[i][j][3] + b2.y;
            *(float2*)(C + (size_t)m * D_ + n) = o0;
            *(float2*)(C + (size_t)(m + 8) * D_ + n) = o1;
        }
    }
}

// ---------------------------------------------------------------------------
// HMMA flash attention, causal, hi/lo split for Q.K^T and P.V.
// CTA: 128 q-rows x (b,h); 8 warps, 16 q-rows each. kv tiles of 64.
// smem (u32, pad 36/row): Qhi/Qlo[128][36], Khi/Klo[64][36], Vthi/Vtlo[64][36]
// P never hits smem: S C-fragments ARE the P.V A-fragments (converted in regs).
// ---------------------------------------------------------------------------
#define FPAD 36
#define FAH_SMEM ((128*FPAD*2 + 64*FPAD*4) * 4)   // 73,728 B

__global__ void __launch_bounds__(256)
flash_hmma(const float* __restrict__ Q, const float* __restrict__ K,
           const float* __restrict__ V, float* __restrict__ ctx)
{
    extern __shared__ uint32_t su[];
    uint32_t* sQhi = su;                    // [128][36]
    uint32_t* sQlo = sQhi + 128 * FPAD;
    uint32_t* sKhi = sQlo + 128 * FPAD;     // [64][36]
    uint32_t* sKlo = sKhi + 64 * FPAD;
    uint32_t* sVhi = sKlo + 64 * FPAD;      // Vt: [dh][kv pairs]
    uint32_t* sVlo = sVhi + 64 * FPAD;

    const int tid = threadIdx.x, wid = tid >> 5, lid = tid & 31;
    const int g = lid >> 2, tc = lid & 3;
    const int bx = blockIdx.x, bh = blockIdx.y;
    const int b = bh / H_, h = bh % H_;
    const int q0 = bx * 128;
    const size_t base = (size_t)b * S_ * D_ + (size_t)h * DH_;
    const int wrow = q0 + wid * 16;     // warp's first q row (global)

    // ---- load Q tile (scaled by 1/8), split hi/lo ----
    #pragma unroll
    for (int i = 0; i < 8; i++) {
        int v = tid + i * 256;              // 0..2047
        int r = v >> 4, c4 = v & 15;
        float4 qv = *(const float4*)(Q + base + (size_t)(q0 + r) * D_ + c4 * 4);
        uint2 h2, l2;
        split2(qv.x * 0.125f, qv.y * 0.125f, h2.x, l2.x);
        split2(qv.z * 0.125f, qv.w * 0.125f, h2.y, l2.y);
        *(uint2*)&sQhi[r * FPAD + c4 * 2] = h2;
        *(uint2*)&sQlo[r * FPAD + c4 * 2] = l2;
    }
    __syncthreads();

    // ---- Q A-fragments into registers (held all kernel) ----
    uint32_t qh[4][4], ql[4][4];
    {
        const int r0 = (wid * 16 + g) * FPAD, r1 = r0 + 8 * FPAD;
        #pragma unroll
        for (int ks = 0; ks < 4; ks++) {
            const int kb = ks * 8 + tc;
            qh[ks][0] = sQhi[r0 + kb];     qh[ks][1] = sQhi[r1 + kb];
            qh[ks][2] = sQhi[r0 + kb + 4]; qh[ks][3] = sQhi[r1 + kb + 4];
            ql[ks][0] = sQlo[r0 + kb];     ql[ks][1] = sQlo[r1 + kb];
            ql[ks][2] = sQlo[r0 + kb + 4]; ql[ks][3] = sQlo[r1 + kb + 4];
        }
    }

    float oacc[8][4];
    #pragma unroll
    for (int j = 0; j < 8; j++)
        #pragma unroll
        for (int q = 0; q < 4; q++) oacc[j][q] = 0.0f;
    float m0r = -1e30f, m1r = -1e30f, l0r = 0.0f, l1r = 0.0f;

    // K LDG map: 64 rows x 16 float4; per thread 4
    const int kr = tid >> 4, kc4 = tid & 15;
    // V LDG map: col vc, row-pair base vr2; 8 passes
    const int vc = tid & 63, vr2 = tid >> 6;

    float4 kv4[4];
    float va[8], vb[8];

    const int ktiles = 2 * (bx + 1);
    // prefetch tile 0
    {
        #pragma unroll
        for (int i = 0; i < 4; i++)
            kv4[i] = *(const float4*)(K + base + (size_t)(kr + i * 16) * D_ + kc4 * 4);
        #pragma unroll
        for (int ii = 0; ii < 8; ii++) {
            int row = (vr2 + ii * 4) * 2;
            va[ii] = V[base + (size_t)row * D_ + vc];
            vb[ii] = V[base + (size_t)(row + 1) * D_ + vc];
        }
    }

    for (int kt = 0; kt < ktiles; kt++) {
        const int k0 = kt * 64;

        // ---- STS K (hi/lo) and Vt (transposed, hi/lo) ----
        #pragma unroll
        for (int i = 0; i < 4; i++) {
            uint2 h2, l2;
            split2(kv4[i].x, kv4[i].y, h2.x, l2.x);
            split2(kv4[i].z, kv4[i].w, h2.y, l2.y);
            *(uint2*)&sKhi[(kr + i * 16) * FPAD + kc4 * 2] = h2;
            *(uint2*)&sKlo[(kr + i * 16) * FPAD + kc4 * 2] = l2;
        }
        #pragma unroll
        for (int ii = 0; ii < 8; ii++) {
            uint32_t hv, lv;
            split2(va[ii], vb[ii], hv, lv);
            sVhi[vc * FPAD + vr2 + ii * 4] = hv;
            sVlo[vc * FPAD + vr2 + ii * 4] = lv;
        }
        __syncthreads();

        // ---- prefetch next tile (overlaps compute) ----
        if (kt + 1 < ktiles) {
            const int kn = (kt + 1) * 64;
            #pragma unroll
            for (int i = 0; i < 4; i++)
                kv4[i] = *(const float4*)(K + base + (size_t)(kn + kr + i * 16) * D_ + kc4 * 4);
            #pragma unroll
            for (int ii = 0; ii < 8; ii++) {
                int row = kn + (vr2 + ii * 4) * 2;
                va[ii] = V[base + (size_t)row * D_ + vc];
                vb[ii] = V[base + (size_t)(row + 1) * D_ + vc];
            }
        }

        // warps entirely above the diagonal skip this tile's compute
        if (k0 <= wrow + 15) {
            // ---- S = Q @ K^T ----
            float sacc[8][4];
            #pragma unroll
            for (int j = 0; j < 8; j++)
                #pragma unroll
                for (int q = 0; q < 4; q++) sacc[j][q] = 0.0f;

            #pragma unroll
            for (int ks = 0; ks < 4; ks++) {
                const int kb = ks * 8 + tc;
                #pragma unroll
                for (int jn = 0; jn < 8; jn++) {
                    const int rn = (jn * 8 + g) * FPAD;
                    uint32_t bhf[2], blf[2];
                    bhf[0] = sKhi[rn + kb]; bhf[1] = sKhi[rn + kb + 4];
                    blf[0] = sKlo[rn + kb]; blf[1] = sKlo[rn + kb + 4];
                    mma16816(sacc[jn], qh[ks], bhf);
                    mma16816(sacc[jn], qh[ks], blf);
                    mma16816(sacc[jn], ql[ks], bhf);
                }
            }

            // ---- causal mask (only diagonal-band tiles) ----
            if (k0 + 63 > wrow) {
                #pragma unroll
                for (int jn = 0; jn < 8; jn++) {
                    const int c0 = k0 + jn * 8 + 2 * tc;
                    const int r0g = wrow + g;
                    if (c0     > r0g)     sacc[jn][0] = -1e30f;
                    if (c0 + 1 > r0g)     sacc[jn][1] = -1e30f;
                    if (c0     > r0g + 8) sacc[jn][2] = -1e30f;
                    if (c0 + 1 > r0g + 8) sacc[jn][3] = -1e30f;
                }
            }

            // ---- online softmax (fp32, quad shfl reductions) ----
            float mt0 = -1e30f, mt1 = -1e30f;
            #pragma unroll
            for (int jn = 0; jn < 8; jn++) {
                mt0 = fmaxf(mt0, fmaxf(sacc[jn][0], sacc[jn][1]));
                mt1 = fmaxf(mt1, fmaxf(sacc[jn][2], sacc[jn][3]));
            }
            mt0 = fmaxf(mt0, __shfl_xor_sync(0xffffffffu, mt0, 1));
            mt0 = fmaxf(mt0, __shfl_xor_sync(0xffffffffu, mt0, 2));
            mt1 = fmaxf(mt1, __shfl_xor_sync(0xffffffffu, mt1, 1));
            mt1 = fmaxf(mt1, __shfl_xor_sync(0xffffffffu, mt1, 2));

            const float mn0 = fmaxf(m0r, mt0), mn1 = fmaxf(m1r, mt1);
            const float al0 = __expf(m0r - mn0), al1 = __expf(m1r - mn1);
            m0r = mn0; m1r = mn1;

            float ls0 = 0.0f, ls1 = 0.0f;
            #pragma unroll
            for (int jn = 0; jn < 8; jn++) {
                sacc[jn][0] = __expf(sacc[jn][0] - mn0);
                sacc[jn][1] = __expf(sacc[jn][1] - mn0);
                sacc[jn][2] = __expf(sacc[jn][2] - mn1);
                sacc[jn][3] = __expf(sacc[jn][3] - mn1);
                ls0 += sacc[jn][0] + sacc[jn][1];
                ls1 += sacc[jn][2] + sacc[jn][3];
            }
            ls0 += __shfl_xor_sync(0xffffffffu, ls0, 1);
            ls0 += __shfl_xor_sync(0xffffffffu, ls0, 2);
            ls1 += __shfl_xor_sync(0xffffffffu, ls1, 1);
            ls1 += __shfl_xor_sync(0xffffffffu, ls1, 2);
            l0r = l0r * al0 + ls0;
            l1r = l1r * al1 + ls1;

            #pragma unroll
            for (int jn = 0; jn < 8; jn++) {
                oacc[jn][0] *= al0; oacc[jn][1] *= al0;
                oacc[jn][2] *= al1; oacc[jn][3] *= al1;
            }

            // ---- O += P @ V  (P from sacc, split hi/lo in regs) ----
            #pragma unroll
            for (int ks = 0; ks < 4; ks++) {
                uint32_t ah[4], al[4];
                split2(sacc[2*ks][0],   sacc[2*ks][1],   ah[0], al[0]);
                split2(sacc[2*ks][2],   sacc[2*ks][3],   ah[1], al[1]);
                split2(sacc[2*ks+1][0], sacc[2*ks+1][1], ah[2], al[2]);
                split2(sacc[2*ks+1][2], sacc[2*ks+1][3], ah[3], al[3]);
                const int kb = ks * 8 + tc;
                #pragma unroll
                for (int jn = 0; jn < 8; jn++) {
                    const int rn = (jn * 8 + g) * FPAD;
                    uint32_t bhf[2], blf[2];
                    bhf[0] = sVhi[rn + kb]; bhf[1] = sVhi[rn + kb + 4];
                    blf[0] = sVlo[rn + kb]; blf[1] = sVlo[rn + kb + 4];
                    mma16816(oacc[jn], ah, bhf);
                    mma16816(oacc[jn], ah, blf);
                    mma16816(oacc[jn], al, bhf);
                }
            }
        }
        __syncthreads();
    }

    // ---- normalize + store ----
    const float inv0 = 1.0f / l0r, inv1 = 1.0f / l1r;
    const int row0 = q0 + wid * 16 + g;
    #pragma unroll
    for (int jn = 0; jn < 8; jn++) {
        const int c = jn * 8 + 2 * tc;
        float2 o0, o1;
        o0.x = oacc[jn][0] * inv0; o0.y = oacc[jn][1] * inv0;
        o1.x = oacc[jn][2] * inv1; o1.y = oacc[jn][3] * inv1;
        *(float2*)(ctx + base + (size_t)row0 * D_ + c) = o0;
        *(float2*)(ctx + base + (size_t)(row0 + 8) * D_ + c) = o1;
    }
}

// ---------------------------------------------------------------------------
// Launch
// Inputs: query, key, value, mask, Wq, bq, Wk, bk, Wv, bv, Wo, bo
// ---------------------------------------------------------------------------
extern "C" void kernel_launch(void* const* d_in, const int* in_sizes, int n_in,
                              void* d_out, int out_size)
{
    const float* query = (const float*)d_in[0];
    const float* key   = (const float*)d_in[1];
    const float* value = (const float*)d_in[2];
    const float* Wq    = (const float*)d_in[4];
    const float* bq    = (const float*)d_in[5];
    const float* Wk    = (const float*)d_in[6];
    const float* bk    = (const float*)d_in[7];
    const float* Wv    = (const float*)d_in[8];
    const float* bv    = (const float*)d_in[9];
    const float* Wo    = (const float*)d_in[10];
    const float* bo    = (const float*)d_in[11];
    float* out = (float*)d_out;

    float *qb, *kb, *vb, *cb;
    cudaGetSymbolAddress((void**)&qb, g_q);
    cudaGetSymbolAddress((void**)&kb, g_k);
    cudaGetSymbolAddress((void**)&vb, g_v);
    cudaGetSymbolAddress((void**)&cb, g_ctx);
    __nv_bfloat16 *whi, *wlo;
    cudaGetSymbolAddress((void**)&whi, g_whi);
    cudaGetSymbolAddress((void**)&wlo, g_wlo);

    cudaFuncSetAttribute(flash_hmma, cudaFuncAttributeMaxDynamicSharedMemorySize, FAH_SMEM);

    const size_t WSZ = (size_t)D_ * D_;
    dim3 pgrid(32, 32), pblk(32, 8);
    prep_w<<<pgrid, pblk>>>(Wq, whi + 0 * WSZ, wlo + 0 * WSZ);
    prep_w<<<pgrid, pblk>>>(Wk, whi + 1 * WSZ, wlo + 1 * WSZ);
    prep_w<<<pgrid, pblk>>>(Wv, whi + 2 * WSZ, wlo + 2 * WSZ);
    prep_w<<<pgrid, pblk>>>(Wo, whi + 3 * WSZ, wlo + 3 * WSZ);

    dim3 ggrid(D_ / 128, MROWS / 128);   // (8, 32)
    gemm_hmma<<<ggrid, 256>>>(query, whi + 0 * WSZ, wlo + 0 * WSZ, bq, qb);
    gemm_hmma<<<ggrid, 256>>>(key,   whi + 1 * WSZ, wlo + 1 * WSZ, bk, kb);
    gemm_hmma<<<ggrid, 256>>>(value, whi + 2 * WSZ, wlo + 2 * WSZ, bv, vb);

    dim3 fgrid(S_ / 128, B_ * H_);       // (16, 32)
    flash_hmma<<<fgrid, 256, FAH_SMEM>>>(qb, kb, vb, cb);

    gemm_hmma<<<ggrid, 256>>>(cb, whi + 3 * WSZ, wlo + 3 * WSZ, bo, out);
}

// round 5
// speedup vs baseline: 2.5542x; 1.0788x over previous
#include <cuda_runtime.h>
#include <cuda_bf16.h>
#include <cstdint>

#define B_  2
#define S_  2048
#define D_  1024
#define H_  16
#define DH_ 64
#define MROWS (B_*S_)   // 4096

// Scratch (allocation-free rule: __device__ globals)
__device__ float g_q[B_ * S_ * D_];
__device__ float g_k[B_ * S_ * D_];
__device__ float g_v[B_ * S_ * D_];
__device__ __nv_bfloat16 g_inhi[3 * MROWS * D_];   // query/key/value hi split
__device__ __nv_bfloat16 g_inlo[3 * MROWS * D_];
__device__ __nv_bfloat16 g_chi[MROWS * D_];        // ctx hi split (flash output)
__device__ __nv_bfloat16 g_clo[MROWS * D_];
__device__ __nv_bfloat16 g_whi[4][D_ * D_];        // W^T hi split, [n][k]
__device__ __nv_bfloat16 g_wlo[4][D_ * D_];

// ---------------------------------------------------------------------------
// Helpers
// ---------------------------------------------------------------------------
__device__ __forceinline__ uint32_t smem_u32(const void* p) {
    uint32_t a;
    asm("{ .reg .u64 t; cvta.to.shared.u64 t, %1; cvt.u32.u64 %0, t; }"
        : "=r"(a) : "l"(p));
    return a;
}

__device__ __forceinline__ void mma16816(float* c, const uint32_t* a, const uint32_t* b) {
    asm volatile(
        "mma.sync.aligned.m16n8k16.row.col.f32.bf16.bf16.f32 "
        "{%0,%1,%2,%3}, {%4,%5,%6,%7}, {%8,%9}, {%0,%1,%2,%3};"
        : "+f"(c[0]), "+f"(c[1]), "+f"(c[2]), "+f"(c[3])
        : "r"(a[0]), "r"(a[1]), "r"(a[2]), "r"(a[3]), "r"(b[0]), "r"(b[1]));
}

__device__ __forceinline__ void split2(float x, float y, uint32_t& hi, uint32_t& lo) {
    __nv_bfloat16 hx = __float2bfloat16(x), hy = __float2bfloat16(y);
    __nv_bfloat16 lx = __float2bfloat16(x - __bfloat162float(hx));
    __nv_bfloat16 ly = __float2bfloat16(y - __bfloat162float(hy));
    hi = ((uint32_t)__bfloat16_as_ushort(hy) << 16) | __bfloat16_as_ushort(hx);
    lo = ((uint32_t)__bfloat16_as_ushort(ly) << 16) | __bfloat16_as_ushort(lx);
}

__device__ __forceinline__ void cp16(uint32_t dst, const void* src) {
    asm volatile("cp.async.cg.shared.global [%0], [%1], 16;" :: "r"(dst), "l"(src));
}
__device__ __forceinline__ void cp_commit() {
    asm volatile("cp.async.commit_group;");
}
__device__ __forceinline__ void cp_wait_all() {
    asm volatile("cp.async.wait_group 0;");
}
__device__ __forceinline__ void ldsm4(uint32_t* r, uint32_t saddr) {
    asm volatile("ldmatrix.sync.aligned.m8n8.x4.shared.b16 {%0,%1,%2,%3}, [%4];"
        : "=r"(r[0]), "=r"(r[1]), "=r"(r[2]), "=r"(r[3]) : "r"(saddr));
}
__device__ __forceinline__ void ldsm2(uint32_t* r, uint32_t saddr) {
    asm volatile("ldmatrix.sync.aligned.m8n8.x2.shared.b16 {%0,%1}, [%2];"
        : "=r"(r[0]), "=r"(r[1]) : "r"(saddr));
}

// ---------------------------------------------------------------------------
// prep_w: W[k][n] fp32 -> Whi/Wlo[n][k] bf16, 4 weights in one launch (z)
// ---------------------------------------------------------------------------
__global__ void prep_w(const float* __restrict__ W0, const float* __restrict__ W1,
                       const float* __restrict__ W2, const float* __restrict__ W3,
                       __nv_bfloat16* __restrict__ Whi, __nv_bfloat16* __restrict__ Wlo)
{
    __shared__ float t[32][33];
    const int z = blockIdx.z;
    const float* W = (z == 0) ? W0 : (z == 1) ? W1 : (z == 2) ? W2 : W3;
    const size_t zoff = (size_t)z * D_ * D_;
    const int n0 = blockIdx.x * 32, k0 = blockIdx.y * 32;
    const int tx = threadIdx.x, ty = threadIdx.y;
    #pragma unroll
    for (int j = 0; j < 32; j += 8)
        t[ty + j][tx] = W[(size_t)(k0 + ty + j) * D_ + n0 + tx];
    __syncthreads();
    #pragma unroll
    for (int j = 0; j < 32; j += 8) {
        float v = t[tx][ty + j];
        __nv_bfloat16 h = __float2bfloat16(v);
        __nv_bfloat16 l = __float2bfloat16(v - __bfloat162float(h));
        size_t o = zoff + (size_t)(n0 + ty + j) * D_ + k0 + tx;
        Whi[o] = h;
        Wlo[o] = l;
    }
}

// ---------------------------------------------------------------------------
// prep_in: fp32 [M,K] -> hi/lo bf16, 3 inputs in one launch (blockIdx.y)
// ---------------------------------------------------------------------------
__global__ void prep_in(const float* __restrict__ q, const float* __restrict__ k,
                        const float* __restrict__ v,
                        __nv_bfloat16* __restrict__ hi, __nv_bfloat16* __restrict__ lo)
{
    const int z = blockIdx.y;
    const float* src = (z == 0) ? q : (z == 1) ? k : v;
    const size_t base4 = (size_t)z * (MROWS * D_ / 4);
    const size_t i = (size_t)blockIdx.x * 256 + threadIdx.x;   // float4 index
    float4 a = ((const float4*)src)[i];
    uint2 h2, l2;
    split2(a.x, a.y, h2.x, l2.x);
    split2(a.z, a.w, h2.y, l2.y);
    ((uint2*)hi)[base4 + i] = h2;
    ((uint2*)lo)[base4 + i] = l2;
}

// ---------------------------------------------------------------------------
// HMMA GEMM, pre-split bf16 hi/lo operands, cp.async double-buffered + ldmatrix.
// C[M,N] = (Ahi+Alo) @ (Whi+Wlo)^T + bias   (3-MMA split, fp32 accum)
// CTA 128x128, BK=32, 8 warps (2m x 4n). Stage = Ahi|Alo|Bhi|Blo, 80B rows.
// ---------------------------------------------------------------------------
#define GPADB 80                         // bytes per smem row (64 data + 16 pad)
#define ARR_B (128 * GPADB)              // 10240 B per array
#define STG_B (4 * ARR_B)                // 40960 B per stage
#define GEMM_SMEM (2 * STG_B)            // 81920 B

__device__ __forceinline__ void gemm_stage_load(
    uint32_t st, int m0, int n0, int k0, int r, int s0,
    const __nv_bfloat16* __restrict__ Ahi, const __nv_bfloat16* __restrict__ Alo,
    const __nv_bfloat16* __restrict__ Whi, const __nv_bfloat16* __restrict__ Wlo)
{
    #pragma unroll
    for (int i = 0; i < 2; i++) {
        const int seg = s0 + i;
        const uint32_t d = st + (uint32_t)(r * GPADB + seg * 16);
        const size_t ea = (size_t)(m0 + r) * D_ + k0 + seg * 8;
        const size_t eb = (size_t)(n0 + r) * D_ + k0 + seg * 8;
        cp16(d,             Ahi + ea);
        cp16(d + ARR_B,     Alo + ea);
        cp16(d + 2 * ARR_B, Whi + eb);
        cp16(d + 3 * ARR_B, Wlo + eb);
    }
}

__global__ void __launch_bounds__(256, 2)
gemm_tc(const __nv_bfloat16* __restrict__ Ahi, const __nv_bfloat16* __restrict__ Alo,
        const __nv_bfloat16* __restrict__ Whi, const __nv_bfloat16* __restrict__ Wlo,
        const float* __restrict__ bias, float* __restrict__ C)
{
    extern __shared__ uint32_t sg[];
    const uint32_t sb = smem_u32(sg);
    const int tid = threadIdx.x, wid = tid >> 5, lid = tid & 31;
    const int g = lid >> 2, tc = lid & 3;
    const int wm = wid & 1, wn = wid >> 1;
    const int m0 = blockIdx.y * 128, n0 = blockIdx.x * 128;

    // cp.async mapping: 2 threads per row, 2 x 16B segments each
    const int r = tid >> 1, s0 = (tid & 1) * 2;

    float acc[4][4][4];
    #pragma unroll
    for (int i = 0; i < 4; i++)
        #pragma unroll
        for (int j = 0; j < 4; j++)
            #pragma unroll
            for (int q = 0; q < 4; q++) acc[i][j][q] = 0.0f;

    // fragment smem address bases (lane-dependent parts)
    const uint32_t a_lane = (uint32_t)((wm * 64 + (lid & 15)) * GPADB + (lid >> 4) * 16);
    const uint32_t b_lane = (uint32_t)((wn * 32 + (lid & 7)) * GPADB + ((lid >> 3) & 1) * 16);

    // prologue: stage 0
    gemm_stage_load(sb, m0, n0, 0, r, s0, Ahi, Alo, Whi, Wlo);
    cp_commit();
    cp_wait_all();
    __syncthreads();

    const int NCH = D_ / 32;   // 32
    for (int ch = 0; ch < NCH; ch++) {
        const int cs = ch & 1;
        if (ch + 1 < NCH) {
            gemm_stage_load(sb + (cs ^ 1) * STG_B, m0, n0, (ch + 1) * 32, r, s0,
                            Ahi, Alo, Whi, Wlo);
            cp_commit();
        }

        const uint32_t st = sb + cs * STG_B;
        #pragma unroll
        for (int ks = 0; ks < 2; ks++) {
            uint32_t bhf[4][2], blf[4][2];
            #pragma unroll
            for (int j = 0; j < 4; j++) {
                const uint32_t ba = st + 2 * ARR_B + b_lane + (uint32_t)(j * 8 * GPADB + ks * 32);
                ldsm2(bhf[j], ba);
                ldsm2(blf[j], ba + ARR_B);
            }
            #pragma unroll
            for (int i = 0; i < 4; i++) {
                uint32_t ah[4], al[4];
                const uint32_t aa = st + a_lane + (uint32_t)(i * 16 * GPADB + ks * 32);
                ldsm4(ah, aa);
                ldsm4(al, aa + ARR_B);
                #pragma unroll
                for (int j = 0; j < 4; j++) {
                    mma16816(acc[i][j], ah, bhf[j]);
                    mma16816(acc[i][j], ah, blf[j]);
                    mma16816(acc[i][j], al, bhf[j]);
                }
            }
        }
        if (ch + 1 < NCH) cp_wait_all();
        __syncthreads();
    }

    // epilogue: bias + store
    #pragma unroll
    for (int j = 0; j < 4; j++) {
        const int n = n0 + wn * 32 + j * 8 + tc * 2;
        const float2 b2 = *(const float2*)(bias + n);
        #pragma unroll
        for (int i = 0; i < 4; i++) {
            const int m = m0 + wm * 64 + i * 16 + g;
            float2 o0, o1;
            o0.x = acc[i][j][0] + b2.x; o0.y = acc[i][j][1] + b2.y;
            o1.x = acc[i][j][2] + b2.x; o1.y = acc[i][j][3] + b2.y;
            *(float2*)(C + (size_t)m * D_ + n) = o0;
            *(float2*)(C + (size_t)(m + 8) * D_ + n) = o1;
        }
    }
}

// ---------------------------------------------------------------------------
// HMMA flash attention, causal, hi/lo split for Q.K^T and P.V.
// CTA: 128 q-rows x (b,h); 8 warps, 16 q-rows each. kv tiles of 64.
// Epilogue writes ctx as hi/lo bf16 (ready for O-projection GEMM).
// ---------------------------------------------------------------------------
#define FPAD 36
#define FAH_SMEM ((128*FPAD*2 + 64*FPAD*4) * 4)   // 73,728 B

__global__ void __launch_bounds__(256)
flash_hmma(const float* __restrict__ Q, const float* __restrict__ K,
           const float* __restrict__ V,
           __nv_bfloat16* __restrict__ chi, __nv_bfloat16* __restrict__ clo)
{
    extern __shared__ uint32_t su[];
    uint32_t* sQhi = su;                    // [128][36]
    uint32_t* sQlo = sQhi + 128 * FPAD;
    uint32_t* sKhi = sQlo + 128 * FPAD;     // [64][36]
    uint32_t* sKlo = sKhi + 64 * FPAD;
    uint32_t* sVhi = sKlo + 64 * FPAD;      // Vt: [dh][kv pairs]
    uint32_t* sVlo = sVhi + 64 * FPAD;

    const int tid = threadIdx.x, wid = tid >> 5, lid = tid & 31;
    const int g = lid >> 2, tc = lid & 3;
    const int bx = blockIdx.x, bh = blockIdx.y;
    const int b = bh / H_, h = bh % H_;
    const int q0 = bx * 128;
    const size_t base = (size_t)b * S_ * D_ + (size_t)h * DH_;
    const int wrow = q0 + wid * 16;

    #pragma unroll
    for (int i = 0; i < 8; i++) {
        int v = tid + i * 256;
        int rr = v >> 4, c4 = v & 15;
        float4 qv = *(const float4*)(Q + base + (size_t)(q0 + rr) * D_ + c4 * 4);
        uint2 h2, l2;
        split2(qv.x * 0.125f, qv.y * 0.125f, h2.x, l2.x);
        split2(qv.z * 0.125f, qv.w * 0.125f, h2.y, l2.y);
        *(uint2*)&sQhi[rr * FPAD + c4 * 2] = h2;
        *(uint2*)&sQlo[rr * FPAD + c4 * 2] = l2;
    }
    __syncthreads();

    uint32_t qh[4][4], ql[4][4];
    {
        const int r0 = (wid * 16 + g) * FPAD, r1 = r0 + 8 * FPAD;
        #pragma unroll
        for (int ks = 0; ks < 4; ks++) {
            const int kb = ks * 8 + tc;
            qh[ks][0] = sQhi[r0 + kb];     qh[ks][1] = sQhi[r1 + kb];
            qh[ks][2] = sQhi[r0 + kb + 4]; qh[ks][3] = sQhi[r1 + kb + 4];
            ql[ks][0] = sQlo[r0 + kb];     ql[ks][1] = sQlo[r1 + kb];
            ql[ks][2] = sQlo[r0 + kb + 4]; ql[ks][3] = sQlo[r1 + kb + 4];
        }
    }

    float oacc[8][4];
    #pragma unroll
    for (int j = 0; j < 8; j++)
        #pragma unroll
        for (int q = 0; q < 4; q++) oacc[j][q] = 0.0f;
    float m0r = -1e30f, m1r = -1e30f, l0r = 0.0f, l1r = 0.0f;

    const int kr = tid >> 4, kc4 = tid & 15;
    const int vc = tid & 63, vr2 = tid >> 6;

    float4 kv4[4];
    float va[8], vb[8];

    const int ktiles = 2 * (bx + 1);
    {
        #pragma unroll
        for (int i = 0; i < 4; i++)
            kv4[i] = *(const float4*)(K + base + (size_t)(kr + i * 16) * D_ + kc4 * 4);
        #pragma unroll
        for (int ii = 0; ii < 8; ii++) {
            int row = (vr2 + ii * 4) * 2;
            va[ii] = V[base + (size_t)row * D_ + vc];
            vb[ii] = V[base + (size_t)(row + 1) * D_ + vc];
        }
    }

    for (int kt = 0; kt < ktiles; kt++) {
        const int k0 = kt * 64;

        #pragma unroll
        for (int i = 0; i < 4; i++) {
            uint2 h2, l2;
            split2(kv4[i].x, kv4[i].y, h2.x, l2.x);
            split2(kv4[i].z, kv4[i].w, h2.y, l2.y);
            *(uint2*)&sKhi[(kr + i * 16) * FPAD + kc4 * 2] = h2;
            *(uint2*)&sKlo[(kr + i * 16) * FPAD + kc4 * 2] = l2;
        }
        #pragma unroll
        for (int ii = 0; ii < 8; ii++) {
            uint32_t hv, lv;
            split2(va[ii], vb[ii], hv, lv);
            sVhi[vc * FPAD + vr2 + ii * 4] = hv;
            sVlo[vc * FPAD + vr2 + ii * 4] = lv;
        }
        __syncthreads();

        if (kt + 1 < ktiles) {
            const int kn = (kt + 1) * 64;
            #pragma unroll
            for (int i = 0; i < 4; i++)
                kv4[i] = *(const float4*)(K + base + (size_t)(kn + kr + i * 16) * D_ + kc4 * 4);
            #pragma unroll
            for (int ii = 0; ii < 8; ii++) {
                int row = kn + (vr2 + ii * 4) * 2;
                va[ii] = V[base + (size_t)row * D_ + vc];
                vb[ii] = V[base + (size_t)(row + 1) * D_ + vc];
            }
        }

        if (k0 <= wrow + 15) {
            float sacc[8][4];
            #pragma unroll
            for (int j = 0; j < 8; j++)
                #pragma unroll
                for (int q = 0; q < 4; q++) sacc[j][q] = 0.0f;

            #pragma unroll
            for (int ks = 0; ks < 4; ks++) {
                const int kb = ks * 8 + tc;
                #pragma unroll
                for (int jn = 0; jn < 8; jn++) {
                    const int rn = (jn * 8 + g) * FPAD;
                    uint32_t bhf[2], blf[2];
                    bhf[0] = sKhi[rn + kb]; bhf[1] = sKhi[rn + kb + 4];
                    blf[0] = sKlo[rn + kb]; blf[1] = sKlo[rn + kb + 4];
                    mma16816(sacc[jn], qh[ks], bhf);
                    mma16816(sacc[jn], qh[ks], blf);
                    mma16816(sacc[jn], ql[ks], bhf);
                }
            }

            if (k0 + 63 > wrow) {
                #pragma unroll
                for (int jn = 0; jn < 8; jn++) {
                    const int c0 = k0 + jn * 8 + 2 * tc;
                    const int r0g = wrow + g;
                    if (c0     > r0g)     sacc[jn][0] = -1e30f;
                    if (c0 + 1 > r0g)     sacc[jn][1] = -1e30f;
                    if (c0     > r0g + 8) sacc[jn][2] = -1e30f;
                    if (c0 + 1 > r0g + 8) sacc[jn][3] = -1e30f;
                }
            }

            float mt0 = -1e30f, mt1 = -1e30f;
            #pragma unroll
            for (int jn = 0; jn < 8; jn++) {
                mt0 = fmaxf(mt0, fmaxf(sacc[jn][0], sacc[jn][1]));
                mt1 = fmaxf(mt1, fmaxf(sacc[jn][2], sacc[jn][3]));
            }
            mt0 = fmaxf(mt0, __shfl_xor_sync(0xffffffffu, mt0, 1));
            mt0 = fmaxf(mt0, __shfl_xor_sync(0xffffffffu, mt0, 2));
            mt1 = fmaxf(mt1, __shfl_xor_sync(0xffffffffu, mt1, 1));
            mt1 = fmaxf(mt1, __shfl_xor_sync(0xffffffffu, mt1, 2));

            const float mn0 = fmaxf(m0r, mt0), mn1 = fmaxf(m1r, mt1);
            const float al0 = __expf(m0r - mn0), al1 = __expf(m1r - mn1);
            m0r = mn0; m1r = mn1;

            float ls0 = 0.0f, ls1 = 0.0f;
            #pragma unroll
            for (int jn = 0; jn < 8; jn++) {
                sacc[jn][0] = __expf(sacc[jn][0] - mn0);
                sacc[jn][1] = __expf(sacc[jn][1] - mn0);
                sacc[jn][2] = __expf(sacc[jn][2] - mn1);
                sacc[jn][3] = __expf(sacc[jn][3] - mn1);
                ls0 += sacc[jn][0] + sacc[jn][1];
                ls1 += sacc[jn][2] + sacc[jn][3];
            }
            ls0 += __shfl_xor_sync(0xffffffffu, ls0, 1);
            ls0 += __shfl_xor_sync(0xffffffffu, ls0, 2);
            ls1 += __shfl_xor_sync(0xffffffffu, ls1, 1);
            ls1 += __shfl_xor_sync(0xffffffffu, ls1, 2);
            l0r = l0r * al0 + ls0;
            l1r = l1r * al1 + ls1;

            #pragma unroll
            for (int jn = 0; jn < 8; jn++) {
                oacc[jn][0] *= al0; oacc[jn][1] *= al0;
                oacc[jn][2] *= al1; oacc[jn][3] *= al1;
            }

            #pragma unroll
            for (int ks = 0; ks < 4; ks++) {
                uint32_t ah[4], al[4];
                split2(sacc[2*ks][0],   sacc[2*ks][1],   ah[0], al[0]);
                split2(sacc[2*ks][2],   sacc[2*ks][3],   ah[1], al[1]);
                split2(sacc[2*ks+1][0], sacc[2*ks+1][1], ah[2], al[2]);
                split2(sacc[2*ks+1][2], sacc[2*ks+1][3], ah[3], al[3]);
                const int kb = ks * 8 + tc;
                #pragma unroll
                for (int jn = 0; jn < 8; jn++) {
                    const int rn = (jn * 8 + g) * FPAD;
                    uint32_t bhf[2], blf[2];
                    bhf[0] = sVhi[rn + kb]; bhf[1] = sVhi[rn + kb + 4];
                    blf[0] = sVlo[rn + kb]; blf[1] = sVlo[rn + kb + 4];
                    mma16816(oacc[jn], ah, bhf);
                    mma16816(oacc[jn], ah, blf);
                    mma16816(oacc[jn], al, bhf);
                }
            }
        }
        __syncthreads();
    }

    // normalize + store ctx as hi/lo bf16 (same split the O-GEMM would do)
    const float inv0 = 1.0f / l0r, inv1 = 1.0f / l1r;
    const int row0 = q0 + wid * 16 + g;
    #pragma unroll
    for (int jn = 0; jn < 8; jn++) {
        const int c = jn * 8 + 2 * tc;
        uint32_t h0, l0, h1, l1;
        split2(oacc[jn][0] * inv0, oacc[jn][1] * inv0, h0, l0);
        split2(oacc[jn][2] * inv1, oacc[jn][3] * inv1, h1, l1);
        const size_t e0 = base + (size_t)row0 * D_ + c;
        const size_t e1 = base + (size_t)(row0 + 8) * D_ + c;
        *(uint32_t*)(chi + e0) = h0;
        *(uint32_t*)(clo + e0) = l0;
        *(uint32_t*)(chi + e1) = h1;
        *(uint32_t*)(clo + e1) = l1;
    }
}

// ---------------------------------------------------------------------------
// Launch
// Inputs: query, key, value, mask, Wq, bq, Wk, bk, Wv, bv, Wo, bo
// ---------------------------------------------------------------------------
extern "C" void kernel_launch(void* const* d_in, const int* in_sizes, int n_in,
                              void* d_out, int out_size)
{
    const float* query = (const float*)d_in[0];
    const float* key   = (const float*)d_in[1];
    const float* value = (const float*)d_in[2];
    const float* Wq    = (const float*)d_in[4];
    const float* bq    = (const float*)d_in[5];
    const float* Wk    = (const float*)d_in[6];
    const float* bk    = (const float*)d_in[7];
    const float* Wv    = (const float*)d_in[8];
    const float* bv    = (const float*)d_in[9];
    const float* Wo    = (const float*)d_in[10];
    const float* bo    = (const float*)d_in[11];
    float* out = (float*)d_out;

    float *qb, *kb, *vb;
    cudaGetSymbolAddress((void**)&qb, g_q);
    cudaGetSymbolAddress((void**)&kb, g_k);
    cudaGetSymbolAddress((void**)&vb, g_v);
    __nv_bfloat16 *inhi, *inlo, *chi, *clo, *whi, *wlo;
    cudaGetSymbolAddress((void**)&inhi, g_inhi);
    cudaGetSymbolAddress((void**)&inlo, g_inlo);
    cudaGetSymbolAddress((void**)&chi, g_chi);
    cudaGetSymbolAddress((void**)&clo, g_clo);
    cudaGetSymbolAddress((void**)&whi, g_whi);
    cudaGetSymbolAddress((void**)&wlo, g_wlo);

    cudaFuncSetAttribute(gemm_tc, cudaFuncAttributeMaxDynamicSharedMemorySize, GEMM_SMEM);
    cudaFuncSetAttribute(flash_hmma, cudaFuncAttributeMaxDynamicSharedMemorySize, FAH_SMEM);

    const size_t WSZ = (size_t)D_ * D_;
    const size_t ISZ = (size_t)MROWS * D_;

    prep_w<<<dim3(32, 32, 4), dim3(32, 8)>>>(Wq, Wk, Wv, Wo, whi, wlo);
    prep_in<<<dim3(MROWS * D_ / 4 / 256, 3), 256>>>(query, key, value, inhi, inlo);

    dim3 ggrid(D_ / 128, MROWS / 128);   // (8, 32)
    gemm_tc<<<ggrid, 256, GEMM_SMEM>>>(inhi + 0 * ISZ, inlo + 0 * ISZ,
                                       whi + 0 * WSZ, wlo + 0 * WSZ, bq, qb);
    gemm_tc<<<ggrid, 256, GEMM_SMEM>>>(inhi + 1 * ISZ, inlo + 1 * ISZ,
                                       whi + 1 * WSZ, wlo + 1 * WSZ, bk, kb);
    gemm_tc<<<ggrid, 256, GEMM_SMEM>>>(inhi + 2 * ISZ, inlo + 2 * ISZ,
                                       whi + 2 * WSZ, wlo + 2 * WSZ, bv, vb);

    dim3 fgrid(S_ / 128, B_ * H_);       // (16, 32)
    flash_hmma<<<fgrid, 256, FAH_SMEM>>>(qb, kb, vb, chi, clo);

    gemm_tc<<<ggrid, 256, GEMM_SMEM>>>(chi, clo, whi + 3 * WSZ, wlo + 3 * WSZ, bo, out);
}